// round 4
// baseline (speedup 1.0000x reference)
#include <cuda_runtime.h>
#include <cuda_bf16.h>
#include <math.h>
#include <stdint.h>

#define T_STEPS 512
#define BATCH   32
#define D_DIM   1024
#define N_DIM   1024
#define R_DIM   8
#define M_ROWS  (T_STEPS*BATCH)   /* 16384 */
#define EPSV    1e-6f

// GEMM tiling
#define GMT 128                  /* M tile */
#define GNT 128                  /* N tile */
#define KC  64                   /* K chunk */
#define NSTEP (D_DIM/KC)         /* 16 */
#define STAGE_BYTES 65536        /* Ahi16K + Alo16K + Bhi16K + Blo16K */
#define SMEM_BYTES  (2*STAGE_BYTES)

// ---------------- scratch (static device allocations; no cudaMalloc) -------
__device__ float g_k[M_ROWS * N_DIM];      // 64 MB
__device__ float g_v[M_ROWS * N_DIM];      // 64 MB
__device__ float g_q[M_ROWS * N_DIM];      // 64 MB
__device__ float g_coef[M_ROWS * 24];      // 1.5 MB
__device__ __nv_bfloat16 g_xhi[M_ROWS * D_DIM];    // 32 MB
__device__ __nv_bfloat16 g_xlo[M_ROWS * D_DIM];    // 32 MB
__device__ __nv_bfloat16 g_whi[3 * N_DIM * D_DIM]; // 6 MB
__device__ __nv_bfloat16 g_wlo[3 * N_DIM * D_DIM]; // 6 MB

// ---------------- fast, accurate transcendentals ---------------------------
__device__ __forceinline__ float tanh_fast(float x) {
    x = fminf(15.f, fmaxf(-15.f, x));
    float e = __expf(2.f * x);
    return __fdividef(e - 1.f, e + 1.f);
}
__device__ __forceinline__ float out_silu(float s) {
    float xs = fminf(30.f, fmaxf(-30.f, s));
    float e  = __expf(-xs);
    float sig = __fdividef(1.f, 1.f + e);
    return s * s * sig;
}

// ---------------- PTX helpers (all baseline sm_80/75 features) -------------
__device__ __forceinline__ uint32_t smem_u32(const void* p) {
    uint32_t a;
    asm("{ .reg .u64 t; cvta.to.shared.u64 t, %1; cvt.u32.u64 %0, t; }"
        : "=r"(a) : "l"(p));
    return a;
}
__device__ __forceinline__ void cp16(uint32_t s, const void* g) {
    asm volatile("cp.async.cg.shared.global [%0], [%1], 16;"
                 :: "r"(s), "l"(g) : "memory");
}
#define LDSM_X4(r0, r1, r2, r3, addr) \
    asm volatile("ldmatrix.sync.aligned.m8n8.x4.shared.b16 {%0,%1,%2,%3}, [%4];" \
        : "=r"(r0), "=r"(r1), "=r"(r2), "=r"(r3) : "r"(addr))
#define MMA_BF16(d, a, b0, b1) \
    asm volatile("mma.sync.aligned.m16n8k16.row.col.f32.bf16.bf16.f32 " \
        "{%0,%1,%2,%3},{%4,%5,%6,%7},{%8,%9},{%0,%1,%2,%3};" \
        : "+f"((d)[0]), "+f"((d)[1]), "+f"((d)[2]), "+f"((d)[3]) \
        : "r"((a)[0]), "r"((a)[1]), "r"((a)[2]), "r"((a)[3]), "r"(b0), "r"(b1))

// ============================================================================
// Conversion kernel: fp32 -> (bf16 hi, bf16 lo) for x and the three weights
// ============================================================================
__global__ __launch_bounds__(256) void convert_kernel(
    const float* __restrict__ x,  const float* __restrict__ Wk,
    const float* __restrict__ Wv, const float* __restrict__ Wq)
{
    int bid = blockIdx.x;
    const float* src;
    __nv_bfloat16 *dh, *dl;
    size_t idx;
    if (bid < 16384) {
        src = x; dh = g_xhi; dl = g_xlo;
        idx = (size_t)bid * 256 + threadIdx.x;
    } else {
        int w  = (bid - 16384) >> 10;
        int lb = (bid - 16384) & 1023;
        src = (w == 0) ? Wk : (w == 1) ? Wv : Wq;
        dh = g_whi + (size_t)w * N_DIM * D_DIM;
        dl = g_wlo + (size_t)w * N_DIM * D_DIM;
        idx = (size_t)lb * 256 + threadIdx.x;
    }
    float4 v = ((const float4*)src)[idx];
    float vv[4] = {v.x, v.y, v.z, v.w};
    __nv_bfloat16 hi[4], lo[4];
#pragma unroll
    for (int j = 0; j < 4; j++) {
        hi[j] = __float2bfloat16_rn(vv[j]);
        lo[j] = __float2bfloat16_rn(vv[j] - __bfloat162float(hi[j]));
    }
    __nv_bfloat162* dh2 = (__nv_bfloat162*)dh;
    __nv_bfloat162* dl2 = (__nv_bfloat162*)dl;
    dh2[idx * 2]     = __nv_bfloat162{hi[0], hi[1]};
    dh2[idx * 2 + 1] = __nv_bfloat162{hi[2], hi[3]};
    dl2[idx * 2]     = __nv_bfloat162{lo[0], lo[1]};
    dl2[idx * 2 + 1] = __nv_bfloat162{lo[2], lo[3]};
}

// ============================================================================
// HMMA GEMM: C[m,n] = sum_k A[m,k]*W[n,k], split-bf16 compensated (3 mma).
// CTA 128x128, 8 warps of 32(M)x64(N), K-chunks of 64, cp.async double buffer.
// Smem stage layout: Ahi @0 (16K), Alo @16K, Bhi @32K, Blo @48K.
// Rows are 64 bf16 = 128B with SW128 swizzle (conflict-free ldmatrix).
// ============================================================================
__device__ __forceinline__ void fill_stage(uint32_t st, int kb, int tid,
    const __nv_bfloat16* __restrict__ Ah, const __nv_bfloat16* __restrict__ Al,
    const __nv_bfloat16* __restrict__ Bh, const __nv_bfloat16* __restrict__ Bl)
{
#pragma unroll
    for (int v = tid; v < 1024; v += 256) {   // 128 rows x 8 chunks of 16B
        int row = v >> 3, c = v & 7;
        uint32_t so = (uint32_t)(row * 128 + ((c * 16) ^ ((row & 7) << 4)));
        size_t go = (size_t)row * D_DIM + kb + c * 8;
        cp16(st + so,         Ah + go);
        cp16(st + 16384 + so, Al + go);
        cp16(st + 32768 + so, Bh + go);
        cp16(st + 49152 + so, Bl + go);
    }
}

__global__ __launch_bounds__(256, 1) void mma_gemm_kernel()
{
    extern __shared__ char smem[];
    const uint32_t sb = smem_u32(smem);
    const int tid  = threadIdx.x;
    const int lane = tid & 31, wid = tid >> 5;
    const int wm = wid >> 1, wn = wid & 1;
    const int nt = blockIdx.x, mt = blockIdx.y, z = blockIdx.z;

    const __nv_bfloat16* Ah = g_xhi + (size_t)mt * GMT * D_DIM;
    const __nv_bfloat16* Al = g_xlo + (size_t)mt * GMT * D_DIM;
    const __nv_bfloat16* Bh = g_whi + (size_t)z * N_DIM * D_DIM + (size_t)nt * GNT * D_DIM;
    const __nv_bfloat16* Bl = g_wlo + (size_t)z * N_DIM * D_DIM + (size_t)nt * GNT * D_DIM;

    // Per-thread ldmatrix offsets
    const uint32_t aRowOff = (uint32_t)((wm * 32 + (lane & 15)) * 128);
    const uint32_t aSeg    = (uint32_t)((lane >> 4) * 16);
    const uint32_t bRowOff = (uint32_t)((wn * 64 + ((lane >> 4) << 3) + (lane & 7)) * 128);
    const uint32_t bSeg    = (uint32_t)(((lane >> 3) & 1) * 16);
    const uint32_t xorm    = (uint32_t)((lane & 7) << 4);

    float acc[2][8][4];
#pragma unroll
    for (int i = 0; i < 2; i++)
#pragma unroll
        for (int j = 0; j < 8; j++)
#pragma unroll
            for (int e = 0; e < 4; e++) acc[i][j][e] = 0.f;

    fill_stage(sb, 0, tid, Ah, Al, Bh, Bl);
    asm volatile("cp.async.commit_group;" ::: "memory");

    for (int c = 0; c < NSTEP; c++) {
        if (c + 1 < NSTEP) {
            fill_stage(sb + ((c + 1) & 1) * STAGE_BYTES, (c + 1) * KC, tid,
                       Ah, Al, Bh, Bl);
            asm volatile("cp.async.commit_group;" ::: "memory");
            asm volatile("cp.async.wait_group 1;" ::: "memory");
        } else {
            asm volatile("cp.async.wait_group 0;" ::: "memory");
        }
        __syncthreads();

        const uint32_t sA = sb + (c & 1) * STAGE_BYTES;
        const uint32_t sB = sA + 32768;

#pragma unroll
        for (int ks = 0; ks < 4; ks++) {
            const uint32_t kb = (uint32_t)(ks * 32);
            uint32_t ah[2][4], al[2][4];
#pragma unroll
            for (int i = 0; i < 2; i++) {
                uint32_t ad = sA + i * 2048 + aRowOff + ((kb + aSeg) ^ xorm);
                LDSM_X4(ah[i][0], ah[i][1], ah[i][2], ah[i][3], ad);
                LDSM_X4(al[i][0], al[i][1], al[i][2], al[i][3], ad + 16384);
            }
            uint32_t bh[8][2], bl[8][2];
#pragma unroll
            for (int jp = 0; jp < 4; jp++) {
                uint32_t bd = sB + jp * 2048 + bRowOff + ((kb + bSeg) ^ xorm);
                LDSM_X4(bh[2*jp][0], bh[2*jp][1], bh[2*jp+1][0], bh[2*jp+1][1], bd);
                LDSM_X4(bl[2*jp][0], bl[2*jp][1], bl[2*jp+1][0], bl[2*jp+1][1], bd + 16384);
            }
#pragma unroll
            for (int i = 0; i < 2; i++)
#pragma unroll
                for (int j = 0; j < 8; j++) {
                    MMA_BF16(acc[i][j], ah[i], bh[j][0], bh[j][1]);
                    MMA_BF16(acc[i][j], ah[i], bl[j][0], bl[j][1]);
                    MMA_BF16(acc[i][j], al[i], bh[j][0], bh[j][1]);
                }
        }
        __syncthreads();
    }

    // Epilogue: direct stores (C-frag: r=lane>>2, c=(lane&3)*2; +8 row pair)
    float* C = (z == 0) ? g_k : (z == 1) ? g_v : g_q;
#pragma unroll
    for (int i = 0; i < 2; i++) {
        const int r0 = mt * GMT + wm * 32 + i * 16 + (lane >> 2);
#pragma unroll
        for (int j = 0; j < 8; j++) {
            const int col = nt * GNT + wn * 64 + j * 8 + (lane & 3) * 2;
            *(float2*)&C[(size_t)r0 * N_DIM + col] =
                make_float2(acc[i][j][0], acc[i][j][1]);
            *(float2*)&C[(size_t)(r0 + 8) * N_DIM + col] =
                make_float2(acc[i][j][2], acc[i][j][3]);
        }
    }
}

// ============================================================================
// Phase B: per (t,b) coefficient reductions
// ============================================================================
__global__ __launch_bounds__(256) void coef_kernel(
    const float* __restrict__ V0, const float* __restrict__ Wkr)
{
    __shared__ float sred[8 * 25];
    __shared__ float sfin[25];

    const int b  = blockIdx.y;
    const int t0 = blockIdx.x * 16;
    const int tid = threadIdx.x;
    const int lane = tid & 31, warp = tid >> 5;

    float Vreg[4][8], Wreg[4][8];
#pragma unroll
    for (int ii = 0; ii < 4; ii++) {
        int i = tid + ii * 256;
        const float4* vp = (const float4*)&V0[(size_t)b * N_DIM * 8 + (size_t)i * 8];
        float4 v0 = vp[0], v1 = vp[1];
        Vreg[ii][0] = v0.x; Vreg[ii][1] = v0.y; Vreg[ii][2] = v0.z; Vreg[ii][3] = v0.w;
        Vreg[ii][4] = v1.x; Vreg[ii][5] = v1.y; Vreg[ii][6] = v1.z; Vreg[ii][7] = v1.w;
#pragma unroll
        for (int j = 0; j < 8; j++) Wreg[ii][j] = Wkr[j * N_DIM + i];
    }

    for (int tt = 0; tt < 16; tt++) {
        const int t = t0 + tt;
        const float* krow = &g_k[(size_t)(t * BATCH + b) * N_DIM];
        const float* qrow = &g_q[(size_t)(t * BATCH + b) * N_DIM];

        float acc[25];
#pragma unroll
        for (int c = 0; c < 25; c++) acc[c] = 0.f;

#pragma unroll
        for (int ii = 0; ii < 4; ii++) {
            int i = tid + ii * 256;
            float kv = krow[i];
            float qv = qrow[i];
            acc[24] = fmaf(kv, kv, acc[24]);
#pragma unroll
            for (int j = 0; j < 8; j++) {
                float vv = Vreg[ii][j];
                acc[j]      = fmaf(vv, kv, acc[j]);
                acc[16 + j] = fmaf(vv, qv, acc[16 + j]);
                acc[8 + j]  = fmaf(Wreg[ii][j], kv, acc[8 + j]);
            }
        }
#pragma unroll
        for (int off = 16; off > 0; off >>= 1)
#pragma unroll
            for (int c = 0; c < 25; c++)
                acc[c] += __shfl_down_sync(0xffffffffu, acc[c], off);

        if (lane == 0) {
#pragma unroll
            for (int c = 0; c < 25; c++) sred[warp * 25 + c] = acc[c];
        }
        __syncthreads();
        if (tid < 25) {
            float s = 0.f;
#pragma unroll
            for (int w = 0; w < 8; w++) s += sred[w * 25 + tid];
            sfin[tid] = s;
        }
        __syncthreads();
        if (tid < 24) {
            float scale = (tid < 16) ? (1.0f / (sqrtf(sfin[24]) + EPSV)) : 1.0f;
            g_coef[(size_t)(t * BATCH + b) * 24 + tid] = sfin[tid] * scale;
        }
        __syncthreads();
    }
}

// ============================================================================
// Phase C: register-resident scan
// ============================================================================
__global__ __launch_bounds__(256) void scan_kernel(
    const float* __restrict__ U0, float* __restrict__ out, int writeExtra)
{
    const int CH = 64;
    __shared__ float sc[CH * 24];

    const int b   = blockIdx.y;
    const int i   = blockIdx.x * 256 + threadIdx.x;
    const int tid = threadIdx.x;

    float U[8];
    {
        const float4* up = (const float4*)&U0[((size_t)b * N_DIM + i) * 8];
        float4 u0 = up[0], u1 = up[1];
        U[0]=u0.x; U[1]=u0.y; U[2]=u0.z; U[3]=u0.w;
        U[4]=u1.x; U[5]=u1.y; U[6]=u1.z; U[7]=u1.w;
    }

    float vcur = g_v[(size_t)b * N_DIM + i];

    for (int tc = 0; tc < T_STEPS; tc += CH) {
        __syncthreads();
        for (int idx = tid; idx < CH * 24; idx += 256) {
            int tt = idx / 24, c = idx - tt * 24;
            sc[idx] = g_coef[(size_t)((tc + tt) * BATCH + b) * 24 + c];
        }
        __syncthreads();

#pragma unroll 2
        for (int tt = 0; tt < CH; tt++) {
            const int t = tc + tt;
            float vnext = (t + 1 < T_STEPS)
                        ? g_v[(size_t)((t + 1) * BATCH + b) * N_DIM + i] : 0.f;
            const float* c = &sc[tt * 24];

            float ret = U[0]*c[0];
#pragma unroll
            for (int j = 1; j < 8; j++) ret = fmaf(U[j], c[j], ret);
            float delta = vcur - ret;

#pragma unroll
            for (int j = 0; j < 8; j++)
                U[j] = tanh_fast(fmaf(delta, c[8 + j], U[j]));

            float sq = U[0]*c[16];
#pragma unroll
            for (int j = 1; j < 8; j++) sq = fmaf(U[j], c[16 + j], sq);

            out[(size_t)(t * BATCH + b) * N_DIM + i] = out_silu(sq);
            vcur = vnext;
        }
    }

    if (writeExtra) {
        float* uf = out + (size_t)M_ROWS * N_DIM + ((size_t)b * N_DIM + i) * 8;
        ((float4*)uf)[0] = make_float4(U[0], U[1], U[2], U[3]);
        ((float4*)uf)[1] = make_float4(U[4], U[5], U[6], U[7]);
    }
}

// ============================================================================
extern "C" void kernel_launch(void* const* d_in, const int* in_sizes, int n_in,
                              void* d_out, int out_size)
{
    const float* x   = (const float*)d_in[0];
    const float* Wk  = (const float*)d_in[1];
    const float* Wv  = (const float*)d_in[2];
    const float* Wq  = (const float*)d_in[3];
    const float* Wkr = (const float*)d_in[4];
    const float* U0  = (const float*)d_in[5];
    const float* V0  = (const float*)d_in[6];
    float* out = (float*)d_out;

    (void)in_sizes; (void)n_in;

    cudaFuncSetAttribute(mma_gemm_kernel,
                         cudaFuncAttributeMaxDynamicSharedMemorySize, SMEM_BYTES);

    // Phase A0: bf16 hi/lo conversion
    convert_kernel<<<16384 + 3 * 1024, 256>>>(x, Wk, Wv, Wq);

    // Phase A: HMMA split-bf16 projections
    mma_gemm_kernel<<<dim3(N_DIM / GNT, M_ROWS / GMT, 3), 256, SMEM_BYTES>>>();

    // Phase B: per-(t,b) coefficient reductions
    coef_kernel<<<dim3(T_STEPS / 16, BATCH), 256>>>(V0, Wkr);

    // Phase C: register-resident scan
    const int extraElems = 2 * BATCH * N_DIM * R_DIM;
    int writeExtra = (out_size >= M_ROWS * N_DIM + extraElems) ? 1 : 0;
    scan_kernel<<<dim3(N_DIM / 256, BATCH), 256>>>(U0, out, writeExtra);

    if (writeExtra) {
        cudaMemcpyAsync(out + (size_t)M_ROWS * N_DIM + BATCH * N_DIM * R_DIM,
                        V0, (size_t)BATCH * N_DIM * R_DIM * sizeof(float),
                        cudaMemcpyDeviceToDevice, 0);
    }
}

// round 7
// speedup vs baseline: 1.2131x; 1.2131x over previous
#include <cuda_runtime.h>
#include <cuda_bf16.h>
#include <math.h>
#include <stdint.h>

#define T_STEPS 512
#define BATCH   32
#define D_DIM   1024
#define N_DIM   1024
#define R_DIM   8
#define M_ROWS  (T_STEPS*BATCH)   /* 16384 */
#define EPSV    1e-6f
#define KC      64
#define NSTEP   (D_DIM/KC)

// ---------------- scratch (static device arrays; no cudaMalloc) ------------
__device__ float g_v[M_ROWS * N_DIM];        // 64 MB
__device__ float g_coef[M_ROWS * 24];        // raw coefs (unscaled)
__device__ float g_nsq[M_ROWS];              // ||k||^2 per (t,b)
__device__ float g_M[384 * 2048];            // fused mats [Wk-side | Wq-side]
__device__ __nv_bfloat16 g_xhi[M_ROWS * D_DIM];
__device__ __nv_bfloat16 g_xlo[M_ROWS * D_DIM];
__device__ __nv_bfloat16 g_wkh[D_DIM * D_DIM];   // Wk hi (norm GEMM)
__device__ __nv_bfloat16 g_wvh[D_DIM * D_DIM];   // Wv hi
__device__ __nv_bfloat16 g_wvl[D_DIM * D_DIM];   // Wv lo

// ---------------- transcendentals -------------------------------------------
__device__ __forceinline__ float tanh_fast(float x) {
    x = fminf(15.f, fmaxf(-15.f, x));
    float e = __expf(2.f * x);
    return __fdividef(e - 1.f, e + 1.f);
}
__device__ __forceinline__ float out_silu(float s) {
    float xs = fminf(30.f, fmaxf(-30.f, s));
    float e  = __expf(-xs);
    return s * s * __fdividef(1.f, 1.f + e);
}

// ---------------- PTX helpers (baseline sm_80 features only) ----------------
__device__ __forceinline__ uint32_t smem_u32(const void* p) {
    uint32_t a;
    asm("{ .reg .u64 t; cvta.to.shared.u64 t, %1; cvt.u32.u64 %0, t; }"
        : "=r"(a) : "l"(p));
    return a;
}
__device__ __forceinline__ void cp16(uint32_t s, const void* g) {
    asm volatile("cp.async.cg.shared.global [%0], [%1], 16;"
                 :: "r"(s), "l"(g) : "memory");
}
#define LDSM_X4(r0, r1, r2, r3, addr) \
    asm volatile("ldmatrix.sync.aligned.m8n8.x4.shared.b16 {%0,%1,%2,%3}, [%4];" \
        : "=r"(r0), "=r"(r1), "=r"(r2), "=r"(r3) : "r"(addr))
#define MMA_BF16(d, a, b0, b1) \
    asm volatile("mma.sync.aligned.m16n8k16.row.col.f32.bf16.bf16.f32 " \
        "{%0,%1,%2,%3},{%4,%5,%6,%7},{%8,%9},{%0,%1,%2,%3};" \
        : "+f"((d)[0]), "+f"((d)[1]), "+f"((d)[2]), "+f"((d)[3]) \
        : "r"((a)[0]), "r"((a)[1]), "r"((a)[2]), "r"((a)[3]), "r"(b0), "r"(b1))

__device__ __forceinline__ void split_hilo(float v, __nv_bfloat16& hi, __nv_bfloat16& lo) {
    hi = __float2bfloat16_rn(v);
    lo = __float2bfloat16_rn(v - __bfloat162float(hi));
}

// ============================================================================
// Convert: x -> hi/lo, Wk -> hi, Wv -> hi/lo; zero g_nsq
// ============================================================================
__global__ __launch_bounds__(256) void convert_kernel(
    const float* __restrict__ x, const float* __restrict__ Wk,
    const float* __restrict__ Wv)
{
    int bid = blockIdx.x;
    if (bid < 16384) {
        size_t idx = (size_t)bid * 256 + threadIdx.x;
        float4 v = ((const float4*)x)[idx];
        float vv[4] = {v.x, v.y, v.z, v.w};
        __nv_bfloat16 hi[4], lo[4];
#pragma unroll
        for (int j = 0; j < 4; j++) split_hilo(vv[j], hi[j], lo[j]);
        ((__nv_bfloat162*)g_xhi)[idx*2]   = __nv_bfloat162{hi[0], hi[1]};
        ((__nv_bfloat162*)g_xhi)[idx*2+1] = __nv_bfloat162{hi[2], hi[3]};
        ((__nv_bfloat162*)g_xlo)[idx*2]   = __nv_bfloat162{lo[0], lo[1]};
        ((__nv_bfloat162*)g_xlo)[idx*2+1] = __nv_bfloat162{lo[2], lo[3]};
    } else if (bid < 17408) {
        size_t idx = (size_t)(bid - 16384) * 256 + threadIdx.x;
        float4 v = ((const float4*)Wk)[idx];
        ((__nv_bfloat162*)g_wkh)[idx*2] =
            __nv_bfloat162{__float2bfloat16_rn(v.x), __float2bfloat16_rn(v.y)};
        ((__nv_bfloat162*)g_wkh)[idx*2+1] =
            __nv_bfloat162{__float2bfloat16_rn(v.z), __float2bfloat16_rn(v.w)};
    } else if (bid < 18432) {
        size_t idx = (size_t)(bid - 17408) * 256 + threadIdx.x;
        float4 v = ((const float4*)Wv)[idx];
        float vv[4] = {v.x, v.y, v.z, v.w};
        __nv_bfloat16 hi[4], lo[4];
#pragma unroll
        for (int j = 0; j < 4; j++) split_hilo(vv[j], hi[j], lo[j]);
        ((__nv_bfloat162*)g_wvh)[idx*2]   = __nv_bfloat162{hi[0], hi[1]};
        ((__nv_bfloat162*)g_wvh)[idx*2+1] = __nv_bfloat162{hi[2], hi[3]};
        ((__nv_bfloat162*)g_wvl)[idx*2]   = __nv_bfloat162{lo[0], lo[1]};
        ((__nv_bfloat162*)g_wvl)[idx*2+1] = __nv_bfloat162{lo[2], lo[3]};
    } else {
        size_t idx = (size_t)(bid - 18432) * 256 + threadIdx.x;
        ((float4*)g_nsq)[idx] = make_float4(0.f, 0.f, 0.f, 0.f);
    }
}

// ============================================================================
// Prep (plain fp32): g_M[p][d]      = sum_n P[p][n] * Wk[n][d]
//                    g_M[p][1024+d] = sum_n P[p][n] * Wq[n][d]
// P rows: p = b*8+j -> V0[b,n,j];  p = 256+j -> Wkr[j,n]
// ============================================================================
__global__ __launch_bounds__(128) void prep_kernel(
    const float* __restrict__ V0, const float* __restrict__ Wk,
    const float* __restrict__ Wq, const float* __restrict__ Wkr)
{
    __shared__ float sP[8][128];
    const int dx  = blockIdx.x;          // 0..15
    const int py  = blockIdx.y;          // 0..32
    const int tid = threadIdx.x;         // 0..127
    const float* W = (dx < 8) ? Wk : Wq;
    const int d = (dx & 7) * 128 + tid;

    float acc[8];
#pragma unroll
    for (int j = 0; j < 8; j++) acc[j] = 0.f;

    for (int n0 = 0; n0 < N_DIM; n0 += 128) {
        __syncthreads();
        for (int idx = tid; idx < 1024; idx += 128) {
            int j = idx >> 7, n = idx & 127;
            float v;
            if (py < 32) v = V0[((size_t)py * N_DIM + n0 + n) * 8 + j];
            else         v = Wkr[(size_t)j * N_DIM + n0 + n];
            sP[j][n] = v;
        }
        __syncthreads();
#pragma unroll 4
        for (int n = 0; n < 128; n++) {
            float w = W[(size_t)(n0 + n) * D_DIM + d];
#pragma unroll
            for (int j = 0; j < 8; j++) acc[j] = fmaf(sP[j][n], w, acc[j]);
        }
    }

    const int prow = py * 8;
    const int dcol = ((dx < 8) ? 0 : 1024) + (dx & 7) * 128 + tid;
#pragma unroll
    for (int j = 0; j < 8; j++)
        g_M[(size_t)(prow + j) * 2048 + dcol] = acc[j];
}

// ============================================================================
// HMMA GEMM. MODE 0 (v): A=g_xhi/g_xlo, B=g_wvh/g_wvl, 3-product, store g_v.
// MODE 1 (norm): A=g_xhi, B=g_wkh, 1 product, row sum-of-squares -> g_nsq.
// Global pointers bound IN DEVICE CODE (host cannot take __device__ addrs).
// ============================================================================
template<int NPROD>
__device__ __forceinline__ void fill_stage(uint32_t st, int kb, int tid,
    const __nv_bfloat16* __restrict__ A0, const __nv_bfloat16* __restrict__ A1,
    const __nv_bfloat16* __restrict__ B0, const __nv_bfloat16* __restrict__ B1)
{
#pragma unroll
    for (int v = tid; v < 1024; v += 256) {
        int row = v >> 3, c = v & 7;
        uint32_t so = (uint32_t)(row * 128 + ((c * 16) ^ ((row & 7) << 4)));
        size_t go = (size_t)row * D_DIM + kb + c * 8;
        if (NPROD == 3) {
            cp16(st + so,         A0 + go);
            cp16(st + 16384 + so, A1 + go);
            cp16(st + 32768 + so, B0 + go);
            cp16(st + 49152 + so, B1 + go);
        } else {
            cp16(st + so,         A0 + go);
            cp16(st + 16384 + so, B0 + go);
        }
    }
}

template<int NPROD, int MODE>
__global__ __launch_bounds__(256, 1) void gemm_kernel()
{
    constexpr int STAGE = (NPROD == 3) ? 65536 : 32768;
    extern __shared__ char smem[];
    const uint32_t sb = smem_u32(smem);
    const int tid  = threadIdx.x;
    const int lane = tid & 31, wid = tid >> 5;
    const int wm = wid >> 1, wn = wid & 1;
    const int nt = blockIdx.x, mt = blockIdx.y;

    // Bind device-global operands here (compile-time by MODE).
    const __nv_bfloat16* Ah = g_xhi;
    const __nv_bfloat16* Al = (MODE == 0) ? g_xlo : g_xhi;
    const __nv_bfloat16* Bh = (MODE == 0) ? g_wvh : g_wkh;
    const __nv_bfloat16* Bl = (MODE == 0) ? g_wvl : g_wkh;
    float* C = g_v;
    const int ldc = N_DIM;

    const __nv_bfloat16* A0 = Ah + (size_t)mt * 128 * D_DIM;
    const __nv_bfloat16* A1 = Al + (size_t)mt * 128 * D_DIM;
    const __nv_bfloat16* B0 = Bh + (size_t)nt * 128 * D_DIM;
    const __nv_bfloat16* B1 = Bl + (size_t)nt * 128 * D_DIM;

    const uint32_t aRowOff = (uint32_t)((wm * 32 + (lane & 15)) * 128);
    const uint32_t aSeg    = (uint32_t)((lane >> 4) * 16);
    const uint32_t bRowOff = (uint32_t)((wn * 64 + ((lane >> 4) << 3) + (lane & 7)) * 128);
    const uint32_t bSeg    = (uint32_t)(((lane >> 3) & 1) * 16);
    const uint32_t xorm    = (uint32_t)((lane & 7) << 4);

    float acc[2][8][4];
#pragma unroll
    for (int i = 0; i < 2; i++)
#pragma unroll
        for (int j = 0; j < 8; j++)
#pragma unroll
            for (int e = 0; e < 4; e++) acc[i][j][e] = 0.f;

    fill_stage<NPROD>(sb, 0, tid, A0, A1, B0, B1);
    asm volatile("cp.async.commit_group;" ::: "memory");

    for (int c = 0; c < NSTEP; c++) {
        if (c + 1 < NSTEP) {
            fill_stage<NPROD>(sb + ((c + 1) & 1) * STAGE, (c + 1) * KC, tid,
                              A0, A1, B0, B1);
            asm volatile("cp.async.commit_group;" ::: "memory");
            asm volatile("cp.async.wait_group 1;" ::: "memory");
        } else {
            asm volatile("cp.async.wait_group 0;" ::: "memory");
        }
        __syncthreads();

        const uint32_t sA = sb + (c & 1) * STAGE;
        const uint32_t sB = sA + ((NPROD == 3) ? 32768 : 16384);

#pragma unroll
        for (int ks = 0; ks < 4; ks++) {
            const uint32_t kb = (uint32_t)(ks * 32);
            uint32_t ah[2][4], al[2][4];
#pragma unroll
            for (int i = 0; i < 2; i++) {
                uint32_t ad = sA + i * 2048 + aRowOff + ((kb + aSeg) ^ xorm);
                LDSM_X4(ah[i][0], ah[i][1], ah[i][2], ah[i][3], ad);
                if (NPROD == 3)
                    LDSM_X4(al[i][0], al[i][1], al[i][2], al[i][3], ad + 16384);
            }
            uint32_t bh[8][2], bl[8][2];
#pragma unroll
            for (int jp = 0; jp < 4; jp++) {
                uint32_t bd = sB + jp * 2048 + bRowOff + ((kb + bSeg) ^ xorm);
                LDSM_X4(bh[2*jp][0], bh[2*jp][1], bh[2*jp+1][0], bh[2*jp+1][1], bd);
                if (NPROD == 3)
                    LDSM_X4(bl[2*jp][0], bl[2*jp][1], bl[2*jp+1][0], bl[2*jp+1][1], bd + 16384);
            }
#pragma unroll
            for (int i = 0; i < 2; i++)
#pragma unroll
                for (int j = 0; j < 8; j++) {
                    MMA_BF16(acc[i][j], ah[i], bh[j][0], bh[j][1]);
                    if (NPROD == 3) {
                        MMA_BF16(acc[i][j], ah[i], bl[j][0], bl[j][1]);
                        MMA_BF16(acc[i][j], al[i], bh[j][0], bh[j][1]);
                    }
                }
        }
        __syncthreads();
    }

    if (MODE == 0) {
#pragma unroll
        for (int i = 0; i < 2; i++) {
            const int r0 = mt * 128 + wm * 32 + i * 16 + (lane >> 2);
#pragma unroll
            for (int j = 0; j < 8; j++) {
                const int col = nt * 128 + wn * 64 + j * 8 + (lane & 3) * 2;
                *(float2*)&C[(size_t)r0 * ldc + col] =
                    make_float2(acc[i][j][0], acc[i][j][1]);
                *(float2*)&C[(size_t)(r0 + 8) * ldc + col] =
                    make_float2(acc[i][j][2], acc[i][j][3]);
            }
        }
    } else {
#pragma unroll
        for (int i = 0; i < 2; i++) {
            float s0 = 0.f, s1 = 0.f;
#pragma unroll
            for (int j = 0; j < 8; j++) {
                s0 = fmaf(acc[i][j][0], acc[i][j][0], s0);
                s0 = fmaf(acc[i][j][1], acc[i][j][1], s0);
                s1 = fmaf(acc[i][j][2], acc[i][j][2], s1);
                s1 = fmaf(acc[i][j][3], acc[i][j][3], s1);
            }
            s0 += __shfl_xor_sync(0xffffffffu, s0, 1);
            s0 += __shfl_xor_sync(0xffffffffu, s0, 2);
            s1 += __shfl_xor_sync(0xffffffffu, s1, 1);
            s1 += __shfl_xor_sync(0xffffffffu, s1, 2);
            const int r0 = mt * 128 + wm * 32 + i * 16 + (lane >> 2);
            if ((lane & 3) == 0) {
                atomicAdd(&g_nsq[r0],     s0);
                atomicAdd(&g_nsq[r0 + 8], s1);
            }
        }
    }
}

// ============================================================================
// Coef: per (t,b), 24 raw dots of x against fused M rows (Vtk | kr | Vtq)
// ============================================================================
__global__ __launch_bounds__(256) void coef_kernel(const float* __restrict__ x)
{
    __shared__ float sred[8 * 24];

    const int b  = blockIdx.y;
    const int t0 = blockIdx.x * 16;
    const int tid = threadIdx.x;
    const int lane = tid & 31, warp = tid >> 5;

    float Mk[4][8], Mr[4][8], Mq[4][8];
#pragma unroll
    for (int ii = 0; ii < 4; ii++) {
        int d = tid + ii * 256;
#pragma unroll
        for (int j = 0; j < 8; j++) {
            Mk[ii][j] = g_M[(size_t)(b * 8 + j) * 2048 + d];
            Mq[ii][j] = g_M[(size_t)(b * 8 + j) * 2048 + 1024 + d];
            Mr[ii][j] = g_M[(size_t)(256 + j) * 2048 + d];
        }
    }

    for (int tt = 0; tt < 16; tt++) {
        const int t = t0 + tt;
        const float* xrow = &x[(size_t)(t * BATCH + b) * D_DIM];

        float acc[24];
#pragma unroll
        for (int c = 0; c < 24; c++) acc[c] = 0.f;

#pragma unroll
        for (int ii = 0; ii < 4; ii++) {
            float xv = xrow[tid + ii * 256];
#pragma unroll
            for (int j = 0; j < 8; j++) {
                acc[j]      = fmaf(Mk[ii][j], xv, acc[j]);
                acc[8 + j]  = fmaf(Mr[ii][j], xv, acc[8 + j]);
                acc[16 + j] = fmaf(Mq[ii][j], xv, acc[16 + j]);
            }
        }
#pragma unroll
        for (int off = 16; off > 0; off >>= 1)
#pragma unroll
            for (int c = 0; c < 24; c++)
                acc[c] += __shfl_down_sync(0xffffffffu, acc[c], off);

        if (lane == 0) {
#pragma unroll
            for (int c = 0; c < 24; c++) sred[warp * 24 + c] = acc[c];
        }
        __syncthreads();
        if (tid < 24) {
            float s = 0.f;
#pragma unroll
            for (int w = 0; w < 8; w++) s += sred[w * 24 + tid];
            g_coef[(size_t)(t * BATCH + b) * 24 + tid] = s;
        }
        __syncthreads();
    }
}

// ============================================================================
// Scan: 2 threads per (b,i) row (h=0/1 own U[0..3]/U[4..7]); dots combined
// via shfl_xor(16). Norm scale applied from g_nsq at use time.
// ============================================================================
__global__ __launch_bounds__(256) void scan_kernel(
    const float* __restrict__ U0, float* __restrict__ out, int writeExtra)
{
    const int CH = 64;
    __shared__ float sc[CH * 24];
    __shared__ float ssc[CH];

    const int b    = blockIdx.y;
    const int tid  = threadIdx.x;
    const int lane = tid & 31, warp = tid >> 5;
    const int h    = lane >> 4;
    const int h4   = h * 4;
    const int i    = blockIdx.x * 128 + warp * 16 + (lane & 15);

    float U[4];
    {
        float4 u = *(const float4*)&U0[((size_t)b * N_DIM + i) * 8 + h4];
        U[0] = u.x; U[1] = u.y; U[2] = u.z; U[3] = u.w;
    }

    float vcur = g_v[(size_t)b * N_DIM + i];   // t = 0

    for (int tc = 0; tc < T_STEPS; tc += CH) {
        __syncthreads();
        if (tid < CH) {
            float ns = g_nsq[(size_t)(tc + tid) * BATCH + b];
            ssc[tid] = __fdividef(1.f, sqrtf(ns) + EPSV);
        }
        for (int idx = tid; idx < CH * 24; idx += 256) {
            int tt = idx / 24;
            sc[idx] = g_coef[(size_t)((tc + tt) * BATCH + b) * 24 + (idx - tt * 24)];
        }
        __syncthreads();

#pragma unroll 2
        for (int tt = 0; tt < CH; tt++) {
            const int t = tc + tt;
            float vnext = (t + 1 < T_STEPS)
                        ? g_v[(size_t)((t + 1) * BATCH + b) * N_DIM + i] : 0.f;
            const float* c = &sc[tt * 24];
            const float s = ssc[tt];

            float part = U[0] * (c[h4] * s);
#pragma unroll
            for (int j = 1; j < 4; j++) part = fmaf(U[j], c[h4 + j] * s, part);
            float ret = part + __shfl_xor_sync(0xffffffffu, part, 16);
            float delta = vcur - ret;

#pragma unroll
            for (int j = 0; j < 4; j++)
                U[j] = tanh_fast(fmaf(delta, c[8 + h4 + j] * s, U[j]));

            float p2 = U[0] * c[16 + h4];
#pragma unroll
            for (int j = 1; j < 4; j++) p2 = fmaf(U[j], c[16 + h4 + j], p2);
            float sq = p2 + __shfl_xor_sync(0xffffffffu, p2, 16);

            if (h == 0)
                out[(size_t)(t * BATCH + b) * N_DIM + i] = out_silu(sq);
            vcur = vnext;
        }
    }

    if (writeExtra) {
        float* uf = out + (size_t)M_ROWS * N_DIM + ((size_t)b * N_DIM + i) * 8 + h4;
        *(float4*)uf = make_float4(U[0], U[1], U[2], U[3]);
    }
}

// ============================================================================
extern "C" void kernel_launch(void* const* d_in, const int* in_sizes, int n_in,
                              void* d_out, int out_size)
{
    const float* x   = (const float*)d_in[0];
    const float* Wk  = (const float*)d_in[1];
    const float* Wv  = (const float*)d_in[2];
    const float* Wq  = (const float*)d_in[3];
    const float* Wkr = (const float*)d_in[4];
    const float* U0  = (const float*)d_in[5];
    const float* V0  = (const float*)d_in[6];
    float* out = (float*)d_out;

    (void)in_sizes; (void)n_in;

    cudaFuncSetAttribute(gemm_kernel<3,0>,
                         cudaFuncAttributeMaxDynamicSharedMemorySize, 131072);
    cudaFuncSetAttribute(gemm_kernel<1,1>,
                         cudaFuncAttributeMaxDynamicSharedMemorySize, 65536);

    // Conversions (+ zero g_nsq)
    convert_kernel<<<18448, 256>>>(x, Wk, Wv);

    // Fused matrices M = P x [Wk | Wq]  (plain fp32)
    prep_kernel<<<dim3(16, 33), 128>>>(V0, Wk, Wq, Wkr);

    // k-norm GEMM (1 product, atomics into g_nsq, no store)
    gemm_kernel<1,1><<<dim3(8, 128), 256, 65536>>>();

    // v GEMM (3-product compensated) -> g_v
    gemm_kernel<3,0><<<dim3(8, 128), 256, 131072>>>();

    // Coefs from fused matrices (full fp32)
    coef_kernel<<<dim3(T_STEPS / 16, BATCH), 256>>>(x);

    // Scan (2 threads per row)
    const int extraElems = 2 * BATCH * N_DIM * R_DIM;
    int writeExtra = (out_size >= M_ROWS * N_DIM + extraElems) ? 1 : 0;
    scan_kernel<<<dim3(N_DIM / 128, BATCH), 256>>>(U0, out, writeExtra);

    if (writeExtra) {
        cudaMemcpyAsync(out + (size_t)M_ROWS * N_DIM + BATCH * N_DIM * R_DIM,
                        V0, (size_t)BATCH * N_DIM * R_DIM * sizeof(float),
                        cudaMemcpyDeviceToDevice, 0);
    }
}

// round 8
// speedup vs baseline: 1.2692x; 1.0463x over previous
#include <cuda_runtime.h>
#include <cuda_bf16.h>
#include <math.h>
#include <stdint.h>

#define T_STEPS 512
#define BATCH   32
#define D_DIM   1024
#define N_DIM   1024
#define R_DIM   8
#define M_ROWS  (T_STEPS*BATCH)   /* 16384 */
#define EPSV    1e-6f
#define KC      64
#define NSTEP   (D_DIM/KC)

// ---------------- scratch (static device arrays; no cudaMalloc) ------------
__device__ float g_v[M_ROWS * N_DIM];        // 64 MB
__device__ float g_coef[M_ROWS * 24];        // raw coefs (unscaled)
__device__ float g_nsq[M_ROWS];              // ||k||^2 per (t,b)
__device__ float g_M[384 * 2048];            // fused mats [Wk-side | Wq-side]
__device__ __nv_bfloat16 g_xhi[M_ROWS * D_DIM];
__device__ __nv_bfloat16 g_xlo[M_ROWS * D_DIM];
__device__ __nv_bfloat16 g_wkh[D_DIM * D_DIM];   // Wk hi (norm GEMM)
__device__ __nv_bfloat16 g_wvh[D_DIM * D_DIM];   // Wv hi
__device__ __nv_bfloat16 g_wvl[D_DIM * D_DIM];   // Wv lo

// ---------------- transcendentals -------------------------------------------
__device__ __forceinline__ float tanh_fast(float x) {
    x = fminf(15.f, fmaxf(-15.f, x));
    float e = __expf(2.f * x);
    return __fdividef(e - 1.f, e + 1.f);
}
__device__ __forceinline__ float out_silu(float s) {
    float xs = fminf(30.f, fmaxf(-30.f, s));
    float e  = __expf(-xs);
    return s * s * __fdividef(1.f, 1.f + e);
}

// ---------------- PTX helpers (baseline sm_80 features only) ----------------
__device__ __forceinline__ uint32_t smem_u32(const void* p) {
    uint32_t a;
    asm("{ .reg .u64 t; cvta.to.shared.u64 t, %1; cvt.u32.u64 %0, t; }"
        : "=r"(a) : "l"(p));
    return a;
}
__device__ __forceinline__ void cp16(uint32_t s, const void* g) {
    asm volatile("cp.async.cg.shared.global [%0], [%1], 16;"
                 :: "r"(s), "l"(g) : "memory");
}
#define LDSM_X4(r0, r1, r2, r3, addr) \
    asm volatile("ldmatrix.sync.aligned.m8n8.x4.shared.b16 {%0,%1,%2,%3}, [%4];" \
        : "=r"(r0), "=r"(r1), "=r"(r2), "=r"(r3) : "r"(addr))
#define MMA_BF16(d, a, b0, b1) \
    asm volatile("mma.sync.aligned.m16n8k16.row.col.f32.bf16.bf16.f32 " \
        "{%0,%1,%2,%3},{%4,%5,%6,%7},{%8,%9},{%0,%1,%2,%3};" \
        : "+f"((d)[0]), "+f"((d)[1]), "+f"((d)[2]), "+f"((d)[3]) \
        : "r"((a)[0]), "r"((a)[1]), "r"((a)[2]), "r"((a)[3]), "r"(b0), "r"(b1))

__device__ __forceinline__ void split_hilo(float v, __nv_bfloat16& hi, __nv_bfloat16& lo) {
    hi = __float2bfloat16_rn(v);
    lo = __float2bfloat16_rn(v - __bfloat162float(hi));
}

// ============================================================================
// Convert: x -> hi/lo, Wk -> hi, Wv -> hi/lo; zero g_nsq
// ============================================================================
__global__ __launch_bounds__(256) void convert_kernel(
    const float* __restrict__ x, const float* __restrict__ Wk,
    const float* __restrict__ Wv)
{
    int bid = blockIdx.x;
    if (bid < 16384) {
        size_t idx = (size_t)bid * 256 + threadIdx.x;
        float4 v = ((const float4*)x)[idx];
        float vv[4] = {v.x, v.y, v.z, v.w};
        __nv_bfloat16 hi[4], lo[4];
#pragma unroll
        for (int j = 0; j < 4; j++) split_hilo(vv[j], hi[j], lo[j]);
        ((__nv_bfloat162*)g_xhi)[idx*2]   = __nv_bfloat162{hi[0], hi[1]};
        ((__nv_bfloat162*)g_xhi)[idx*2+1] = __nv_bfloat162{hi[2], hi[3]};
        ((__nv_bfloat162*)g_xlo)[idx*2]   = __nv_bfloat162{lo[0], lo[1]};
        ((__nv_bfloat162*)g_xlo)[idx*2+1] = __nv_bfloat162{lo[2], lo[3]};
    } else if (bid < 17408) {
        size_t idx = (size_t)(bid - 16384) * 256 + threadIdx.x;
        float4 v = ((const float4*)Wk)[idx];
        ((__nv_bfloat162*)g_wkh)[idx*2] =
            __nv_bfloat162{__float2bfloat16_rn(v.x), __float2bfloat16_rn(v.y)};
        ((__nv_bfloat162*)g_wkh)[idx*2+1] =
            __nv_bfloat162{__float2bfloat16_rn(v.z), __float2bfloat16_rn(v.w)};
    } else if (bid < 18432) {
        size_t idx = (size_t)(bid - 17408) * 256 + threadIdx.x;
        float4 v = ((const float4*)Wv)[idx];
        float vv[4] = {v.x, v.y, v.z, v.w};
        __nv_bfloat16 hi[4], lo[4];
#pragma unroll
        for (int j = 0; j < 4; j++) split_hilo(vv[j], hi[j], lo[j]);
        ((__nv_bfloat162*)g_wvh)[idx*2]   = __nv_bfloat162{hi[0], hi[1]};
        ((__nv_bfloat162*)g_wvh)[idx*2+1] = __nv_bfloat162{hi[2], hi[3]};
        ((__nv_bfloat162*)g_wvl)[idx*2]   = __nv_bfloat162{lo[0], lo[1]};
        ((__nv_bfloat162*)g_wvl)[idx*2+1] = __nv_bfloat162{lo[2], lo[3]};
    } else {
        size_t idx = (size_t)(bid - 18432) * 256 + threadIdx.x;
        ((float4*)g_nsq)[idx] = make_float4(0.f, 0.f, 0.f, 0.f);
    }
}

// ============================================================================
// Prep (plain fp32): g_M[p][d] = sum_n P[p][n]*Wk[n][d]; [.][1024+d] for Wq.
// ============================================================================
__global__ __launch_bounds__(128) void prep_kernel(
    const float* __restrict__ V0, const float* __restrict__ Wk,
    const float* __restrict__ Wq, const float* __restrict__ Wkr)
{
    __shared__ float sP[8][128];
    const int dx  = blockIdx.x;          // 0..15
    const int py  = blockIdx.y;          // 0..32
    const int tid = threadIdx.x;         // 0..127
    const float* W = (dx < 8) ? Wk : Wq;
    const int d = (dx & 7) * 128 + tid;

    float acc[8];
#pragma unroll
    for (int j = 0; j < 8; j++) acc[j] = 0.f;

    for (int n0 = 0; n0 < N_DIM; n0 += 128) {
        __syncthreads();
        for (int idx = tid; idx < 1024; idx += 128) {
            int j = idx >> 7, n = idx & 127;
            float v;
            if (py < 32) v = V0[((size_t)py * N_DIM + n0 + n) * 8 + j];
            else         v = Wkr[(size_t)j * N_DIM + n0 + n];
            sP[j][n] = v;
        }
        __syncthreads();
#pragma unroll 4
        for (int n = 0; n < 128; n++) {
            float w = W[(size_t)(n0 + n) * D_DIM + d];
#pragma unroll
            for (int j = 0; j < 8; j++) acc[j] = fmaf(sP[j][n], w, acc[j]);
        }
    }

    const int prow = py * 8;
    const int dcol = ((dx < 8) ? 0 : 1024) + (dx & 7) * 128 + tid;
#pragma unroll
    for (int j = 0; j < 8; j++)
        g_M[(size_t)(prow + j) * 2048 + dcol] = acc[j];
}

// ============================================================================
// HMMA GEMM, 3-stage cp.async pipeline.
// MODE 0 (v): 3-product compensated, store g_v. MODE 1 (norm): 1 product,
// row sum-of-squares -> atomicAdd g_nsq. Globals bound in device code.
// ============================================================================
template<int NPROD>
__device__ __forceinline__ void fill_stage(uint32_t st, int kb, int tid,
    const __nv_bfloat16* __restrict__ A0, const __nv_bfloat16* __restrict__ A1,
    const __nv_bfloat16* __restrict__ B0, const __nv_bfloat16* __restrict__ B1)
{
#pragma unroll
    for (int v = tid; v < 1024; v += 256) {
        int row = v >> 3, c = v & 7;
        uint32_t so = (uint32_t)(row * 128 + ((c * 16) ^ ((row & 7) << 4)));
        size_t go = (size_t)row * D_DIM + kb + c * 8;
        if (NPROD == 3) {
            cp16(st + so,         A0 + go);
            cp16(st + 16384 + so, A1 + go);
            cp16(st + 32768 + so, B0 + go);
            cp16(st + 49152 + so, B1 + go);
        } else {
            cp16(st + so,         A0 + go);
            cp16(st + 16384 + so, B0 + go);
        }
    }
}

template<int NPROD, int MODE>
__global__ __launch_bounds__(256, 1) void gemm_kernel()
{
    constexpr int STAGE = (NPROD == 3) ? 65536 : 32768;
    extern __shared__ char smem[];
    const uint32_t sb = smem_u32(smem);
    const int tid  = threadIdx.x;
    const int lane = tid & 31, wid = tid >> 5;
    const int wm = wid >> 1, wn = wid & 1;
    const int nt = blockIdx.x, mt = blockIdx.y;

    const __nv_bfloat16* Ah = g_xhi;
    const __nv_bfloat16* Al = (MODE == 0) ? g_xlo : g_xhi;
    const __nv_bfloat16* Bh = (MODE == 0) ? g_wvh : g_wkh;
    const __nv_bfloat16* Bl = (MODE == 0) ? g_wvl : g_wkh;
    float* C = g_v;
    const int ldc = N_DIM;

    const __nv_bfloat16* A0 = Ah + (size_t)mt * 128 * D_DIM;
    const __nv_bfloat16* A1 = Al + (size_t)mt * 128 * D_DIM;
    const __nv_bfloat16* B0 = Bh + (size_t)nt * 128 * D_DIM;
    const __nv_bfloat16* B1 = Bl + (size_t)nt * 128 * D_DIM;

    const uint32_t aRowOff = (uint32_t)((wm * 32 + (lane & 15)) * 128);
    const uint32_t aSeg    = (uint32_t)((lane >> 4) * 16);
    const uint32_t bRowOff = (uint32_t)((wn * 64 + ((lane >> 4) << 3) + (lane & 7)) * 128);
    const uint32_t bSeg    = (uint32_t)(((lane >> 3) & 1) * 16);
    const uint32_t xorm    = (uint32_t)((lane & 7) << 4);

    float acc[2][8][4];
#pragma unroll
    for (int i = 0; i < 2; i++)
#pragma unroll
        for (int j = 0; j < 8; j++)
#pragma unroll
            for (int e = 0; e < 4; e++) acc[i][j][e] = 0.f;

    // 3-stage prologue
    fill_stage<NPROD>(sb, 0, tid, A0, A1, B0, B1);
    asm volatile("cp.async.commit_group;" ::: "memory");
    fill_stage<NPROD>(sb + STAGE, KC, tid, A0, A1, B0, B1);
    asm volatile("cp.async.commit_group;" ::: "memory");

    for (int c = 0; c < NSTEP; c++) {
        if (c + 2 < NSTEP) {
            fill_stage<NPROD>(sb + ((c + 2) % 3) * STAGE, (c + 2) * KC, tid,
                              A0, A1, B0, B1);
            asm volatile("cp.async.commit_group;" ::: "memory");
            asm volatile("cp.async.wait_group 2;" ::: "memory");
        } else if (c + 1 < NSTEP) {
            asm volatile("cp.async.wait_group 1;" ::: "memory");
        } else {
            asm volatile("cp.async.wait_group 0;" ::: "memory");
        }
        __syncthreads();

        const uint32_t sA = sb + (c % 3) * STAGE;
        const uint32_t sB = sA + ((NPROD == 3) ? 32768 : 16384);

#pragma unroll
        for (int ks = 0; ks < 4; ks++) {
            const uint32_t kb = (uint32_t)(ks * 32);
            uint32_t ah[2][4], al[2][4];
#pragma unroll
            for (int i = 0; i < 2; i++) {
                uint32_t ad = sA + i * 2048 + aRowOff + ((kb + aSeg) ^ xorm);
                LDSM_X4(ah[i][0], ah[i][1], ah[i][2], ah[i][3], ad);
                if (NPROD == 3)
                    LDSM_X4(al[i][0], al[i][1], al[i][2], al[i][3], ad + 16384);
            }
            uint32_t bh[8][2], bl[8][2];
#pragma unroll
            for (int jp = 0; jp < 4; jp++) {
                uint32_t bd = sB + jp * 2048 + bRowOff + ((kb + bSeg) ^ xorm);
                LDSM_X4(bh[2*jp][0], bh[2*jp][1], bh[2*jp+1][0], bh[2*jp+1][1], bd);
                if (NPROD == 3)
                    LDSM_X4(bl[2*jp][0], bl[2*jp][1], bl[2*jp+1][0], bl[2*jp+1][1], bd + 16384);
            }
#pragma unroll
            for (int i = 0; i < 2; i++)
#pragma unroll
                for (int j = 0; j < 8; j++) {
                    MMA_BF16(acc[i][j], ah[i], bh[j][0], bh[j][1]);
                    if (NPROD == 3) {
                        MMA_BF16(acc[i][j], ah[i], bl[j][0], bl[j][1]);
                        MMA_BF16(acc[i][j], al[i], bh[j][0], bh[j][1]);
                    }
                }
        }
        __syncthreads();
    }

    if (MODE == 0) {
#pragma unroll
        for (int i = 0; i < 2; i++) {
            const int r0 = mt * 128 + wm * 32 + i * 16 + (lane >> 2);
#pragma unroll
            for (int j = 0; j < 8; j++) {
                const int col = nt * 128 + wn * 64 + j * 8 + (lane & 3) * 2;
                *(float2*)&C[(size_t)r0 * ldc + col] =
                    make_float2(acc[i][j][0], acc[i][j][1]);
                *(float2*)&C[(size_t)(r0 + 8) * ldc + col] =
                    make_float2(acc[i][j][2], acc[i][j][3]);
            }
        }
    } else {
#pragma unroll
        for (int i = 0; i < 2; i++) {
            float s0 = 0.f, s1 = 0.f;
#pragma unroll
            for (int j = 0; j < 8; j++) {
                s0 = fmaf(acc[i][j][0], acc[i][j][0], s0);
                s0 = fmaf(acc[i][j][1], acc[i][j][1], s0);
                s1 = fmaf(acc[i][j][2], acc[i][j][2], s1);
                s1 = fmaf(acc[i][j][3], acc[i][j][3], s1);
            }
            s0 += __shfl_xor_sync(0xffffffffu, s0, 1);
            s0 += __shfl_xor_sync(0xffffffffu, s0, 2);
            s1 += __shfl_xor_sync(0xffffffffu, s1, 1);
            s1 += __shfl_xor_sync(0xffffffffu, s1, 2);
            const int r0 = mt * 128 + wm * 32 + i * 16 + (lane >> 2);
            if ((lane & 3) == 0) {
                atomicAdd(&g_nsq[r0],     s0);
                atomicAdd(&g_nsq[r0 + 8], s1);
            }
        }
    }
}

// ============================================================================
// Coef: per (t,b), 24 raw dots of x against fused M rows (Vtk | kr | Vtq)
// ============================================================================
__global__ __launch_bounds__(256) void coef_kernel(const float* __restrict__ x)
{
    __shared__ float sred[8 * 24];

    const int b  = blockIdx.y;
    const int t0 = blockIdx.x * 16;
    const int tid = threadIdx.x;
    const int lane = tid & 31, warp = tid >> 5;

    float Mk[4][8], Mr[4][8], Mq[4][8];
#pragma unroll
    for (int ii = 0; ii < 4; ii++) {
        int d = tid + ii * 256;
#pragma unroll
        for (int j = 0; j < 8; j++) {
            Mk[ii][j] = g_M[(size_t)(b * 8 + j) * 2048 + d];
            Mq[ii][j] = g_M[(size_t)(b * 8 + j) * 2048 + 1024 + d];
            Mr[ii][j] = g_M[(size_t)(256 + j) * 2048 + d];
        }
    }

    for (int tt = 0; tt < 16; tt++) {
        const int t = t0 + tt;
        const float* xrow = &x[(size_t)(t * BATCH + b) * D_DIM];

        float acc[24];
#pragma unroll
        for (int c = 0; c < 24; c++) acc[c] = 0.f;

#pragma unroll
        for (int ii = 0; ii < 4; ii++) {
            float xv = xrow[tid + ii * 256];
#pragma unroll
            for (int j = 0; j < 8; j++) {
                acc[j]      = fmaf(Mk[ii][j], xv, acc[j]);
                acc[8 + j]  = fmaf(Mr[ii][j], xv, acc[8 + j]);
                acc[16 + j] = fmaf(Mq[ii][j], xv, acc[16 + j]);
            }
        }
#pragma unroll
        for (int off = 16; off > 0; off >>= 1)
#pragma unroll
            for (int c = 0; c < 24; c++)
                acc[c] += __shfl_down_sync(0xffffffffu, acc[c], off);

        if (lane == 0) {
#pragma unroll
            for (int c = 0; c < 24; c++) sred[warp * 24 + c] = acc[c];
        }
        __syncthreads();
        if (tid < 24) {
            float s = 0.f;
#pragma unroll
            for (int w = 0; w < 8; w++) s += sred[w * 24 + tid];
            g_coef[(size_t)(t * BATCH + b) * 24 + tid] = s;
        }
        __syncthreads();
    }
}

// ============================================================================
// Scan: 2 threads per (b,i) row; dots combined via shfl_xor(16).
// ============================================================================
__global__ __launch_bounds__(256) void scan_kernel(
    const float* __restrict__ U0, float* __restrict__ out, int writeExtra)
{
    const int CH = 64;
    __shared__ float sc[CH * 24];
    __shared__ float ssc[CH];

    const int b    = blockIdx.y;
    const int tid  = threadIdx.x;
    const int lane = tid & 31, warp = tid >> 5;
    const int h    = lane >> 4;
    const int h4   = h * 4;
    const int i    = blockIdx.x * 128 + warp * 16 + (lane & 15);

    float U[4];
    {
        float4 u = *(const float4*)&U0[((size_t)b * N_DIM + i) * 8 + h4];
        U[0] = u.x; U[1] = u.y; U[2] = u.z; U[3] = u.w;
    }

    float vcur = g_v[(size_t)b * N_DIM + i];   // t = 0

    for (int tc = 0; tc < T_STEPS; tc += CH) {
        __syncthreads();
        if (tid < CH) {
            float ns = g_nsq[(size_t)(tc + tid) * BATCH + b];
            ssc[tid] = __fdividef(1.f, sqrtf(ns) + EPSV);
        }
        for (int idx = tid; idx < CH * 24; idx += 256) {
            int tt = idx / 24;
            sc[idx] = g_coef[(size_t)((tc + tt) * BATCH + b) * 24 + (idx - tt * 24)];
        }
        __syncthreads();

#pragma unroll 2
        for (int tt = 0; tt < CH; tt++) {
            const int t = tc + tt;
            float vnext = (t + 1 < T_STEPS)
                        ? g_v[(size_t)((t + 1) * BATCH + b) * N_DIM + i] : 0.f;
            const float* c = &sc[tt * 24];
            const float s = ssc[tt];

            float part = U[0] * (c[h4] * s);
#pragma unroll
            for (int j = 1; j < 4; j++) part = fmaf(U[j], c[h4 + j] * s, part);
            float ret = part + __shfl_xor_sync(0xffffffffu, part, 16);
            float delta = vcur - ret;

#pragma unroll
            for (int j = 0; j < 4; j++)
                U[j] = tanh_fast(fmaf(delta, c[8 + h4 + j] * s, U[j]));

            float p2 = U[0] * c[16 + h4];
#pragma unroll
            for (int j = 1; j < 4; j++) p2 = fmaf(U[j], c[16 + h4 + j], p2);
            float sq = p2 + __shfl_xor_sync(0xffffffffu, p2, 16);

            if (h == 0)
                out[(size_t)(t * BATCH + b) * N_DIM + i] = out_silu(sq);
            vcur = vnext;
        }
    }

    if (writeExtra) {
        float* uf = out + (size_t)M_ROWS * N_DIM + ((size_t)b * N_DIM + i) * 8 + h4;
        *(float4*)uf = make_float4(U[0], U[1], U[2], U[3]);
    }
}

// ============================================================================
struct AuxStreams {
    cudaStream_t s2;
    cudaEvent_t  fork, join;
    AuxStreams() {
        cudaStreamCreate(&s2);
        cudaEventCreateWithFlags(&fork, cudaEventDisableTiming);
        cudaEventCreateWithFlags(&join, cudaEventDisableTiming);
    }
};

extern "C" void kernel_launch(void* const* d_in, const int* in_sizes, int n_in,
                              void* d_out, int out_size)
{
    const float* x   = (const float*)d_in[0];
    const float* Wk  = (const float*)d_in[1];
    const float* Wv  = (const float*)d_in[2];
    const float* Wq  = (const float*)d_in[3];
    const float* Wkr = (const float*)d_in[4];
    const float* U0  = (const float*)d_in[5];
    const float* V0  = (const float*)d_in[6];
    float* out = (float*)d_out;

    (void)in_sizes; (void)n_in;

    static AuxStreams aux;   // created on first (uncaptured) correctness call

    cudaFuncSetAttribute(gemm_kernel<3,0>,
                         cudaFuncAttributeMaxDynamicSharedMemorySize, 196608);
    cudaFuncSetAttribute(gemm_kernel<1,1>,
                         cudaFuncAttributeMaxDynamicSharedMemorySize, 98304);

    // Fork side chain B: prep -> coef (fp32 FMA; independent of chain A)
    cudaEventRecord(aux.fork, 0);
    cudaStreamWaitEvent(aux.s2, aux.fork, 0);
    prep_kernel<<<dim3(16, 33), 128, 0, aux.s2>>>(V0, Wk, Wq, Wkr);
    coef_kernel<<<dim3(T_STEPS / 16, BATCH), 256, 0, aux.s2>>>(x);
    cudaEventRecord(aux.join, aux.s2);

    // Chain A (stream 0): convert -> norm-GEMM -> v-GEMM
    convert_kernel<<<18448, 256>>>(x, Wk, Wv);
    gemm_kernel<1,1><<<dim3(8, 128), 256, 98304>>>();
    gemm_kernel<3,0><<<dim3(8, 128), 256, 196608>>>();

    // Join, then scan
    cudaStreamWaitEvent(0, aux.join, 0);
    const int extraElems = 2 * BATCH * N_DIM * R_DIM;
    int writeExtra = (out_size >= M_ROWS * N_DIM + extraElems) ? 1 : 0;
    scan_kernel<<<dim3(N_DIM / 128, BATCH), 256>>>(U0, out, writeExtra);

    if (writeExtra) {
        cudaMemcpyAsync(out + (size_t)M_ROWS * N_DIM + BATCH * N_DIM * R_DIM,
                        V0, (size_t)BATCH * N_DIM * R_DIM * sizeof(float),
                        cudaMemcpyDeviceToDevice, 0);
    }
}